// round 1
// baseline (speedup 1.0000x reference)
#include <cuda_runtime.h>
#include <cstdint>

// Problem constants
#define NB    16
#define PIX   784        // 28*28
#define NPOS  12544      // 16*784
#define CIN   1024
#define WIDTH 256
#define COUT  1024

// -------- device scratch (no allocations allowed) --------
__device__ uint32_t g_x8[NPOS * CIN / 4];          // x, NHWC int8 packed  (12.8 MB)
__device__ uint32_t g_w1[WIDTH * CIN / 4];         // [co][ci] int8
__device__ uint32_t g_w2[WIDTH * 9 * WIDTH / 4];   // [co][tap][ci] int8
__device__ uint32_t g_w3[COUT * WIDTH / 4];        // [co][ci] int8
__device__ uint32_t g_a1[NPOS * WIDTH / 4];        // act1 NHWC int8
__device__ uint32_t g_a2[NPOS * WIDTH / 4];        // act2 NHWC int8

static __device__ __forceinline__ uint32_t pack4(int v0, int v1, int v2, int v3) {
    return (uint32_t)(uint8_t)(int8_t)v0 |
           ((uint32_t)(uint8_t)(int8_t)v1 << 8) |
           ((uint32_t)(uint8_t)(int8_t)v2 << 16) |
           ((uint32_t)(uint8_t)(int8_t)v3 << 24);
}

// BN + clip + relu (layers 1,2).  Matches reference fp32 semantics:
// round((alpha*c + beta*2^(q+12)) * 2^-12), round = half-to-even (rintf).
static __device__ __forceinline__ int bn_clip_relu(int acc, float a, float b, float qq) {
    float t = __fadd_rn(__fmul_rn(a, (float)acc), __fmul_rn(b, qq));
    float r = rintf(t * (1.0f / 4096.0f));
    r = fminf(fmaxf(r, -128.0f), 127.0f);
    r = fmaxf(r, 0.0f);
    return (int)r;
}

// BN + clip only (layer 3)
static __device__ __forceinline__ float bn_clip(int acc, float a, float b, float qq) {
    float t = __fadd_rn(__fmul_rn(a, (float)acc), __fmul_rn(b, qq));
    float r = rintf(t * (1.0f / 4096.0f));
    return fminf(fmaxf(r, -128.0f), 127.0f);
}

// -------------------- weight packing --------------------
__global__ void pack_w1_kernel(const float* __restrict__ w, const int* __restrict__ s) {
    int wi = blockIdx.x * blockDim.x + threadIdx.x;
    if (wi >= WIDTH * CIN / 4) return;
    int v[4];
#pragma unroll
    for (int j = 0; j < 4; j++) {
        int idx = wi * 4 + j;
        v[j] = (int)w[idx] * (1 << s[idx]);
    }
    g_w1[wi] = pack4(v[0], v[1], v[2], v[3]);
}

__global__ void pack_w3_kernel(const float* __restrict__ w, const int* __restrict__ s) {
    int wi = blockIdx.x * blockDim.x + threadIdx.x;
    if (wi >= COUT * WIDTH / 4) return;
    int v[4];
#pragma unroll
    for (int j = 0; j < 4; j++) {
        int idx = wi * 4 + j;
        v[j] = (int)w[idx] * (1 << s[idx]);
    }
    g_w3[wi] = pack4(v[0], v[1], v[2], v[3]);
}

// src layout OIHW: [co][ci][kh][kw]  ->  dst [co][tap][ci] packed
__global__ void pack_w2_kernel(const float* __restrict__ w, const int* __restrict__ s) {
    int wi = blockIdx.x * blockDim.x + threadIdx.x;
    if (wi >= WIDTH * 9 * WIDTH / 4) return;
    int co  = wi / 576;            // 576 = 9*256/4 words per co
    int rr  = wi - co * 576;
    int tap = rr >> 6;             // /64
    int cw  = rr & 63;
    int v[4];
#pragma unroll
    for (int j = 0; j < 4; j++) {
        int ci  = cw * 4 + j;
        int src = co * 2304 + ci * 9 + tap;
        v[j] = (int)w[src] * (1 << s[src]);
    }
    g_w2[wi] = pack4(v[0], v[1], v[2], v[3]);
}

// -------------------- NCHW int32 -> NHWC int8 transpose --------------------
// tile: 32 spatial x 32 words (=128 channels), SMEM-staged so both sides coalesce
__global__ void xpose_kernel(const int* __restrict__ x) {
    __shared__ uint32_t s[32][33];
    int t = threadIdx.x;
    int bx = blockIdx.x;   // phw tile (25 tiles of 32, last partial)
    int by = blockIdx.y;   // channel-word tile (8 tiles of 32 words)
    int n  = blockIdx.z;

    int phw_l = t & 31;
    int phw = bx * 32 + phw_l;
#pragma unroll
    for (int l = 0; l < 4; l++) {
        int cwl = (t >> 5) + l * 8;
        uint32_t wv = 0;
        if (phw < PIX) {
            int ci = by * 128 + cwl * 4;
            const int* p = x + ((size_t)n * CIN + ci) * PIX + phw;
            wv = pack4(p[0], p[PIX], p[2 * PIX], p[3 * PIX]);
        }
        s[phw_l][cwl] = wv;
    }
    __syncthreads();
    int cwl2 = t & 31;
#pragma unroll
    for (int l = 0; l < 4; l++) {
        int pl = (t >> 5) + l * 8;
        int phw2 = bx * 32 + pl;
        if (phw2 < PIX)
            g_x8[((size_t)(n * PIX + phw2)) * 256 + by * 32 + cwl2] = s[pl][cwl2];
    }
}

// -------------------- conv1: 1x1, K=1024 (256 words) --------------------
__global__ void __launch_bounds__(256) conv1_kernel(const float* __restrict__ alpha,
                                                    const float* __restrict__ beta,
                                                    const int* __restrict__ q) {
    __shared__ uint32_t As[64][17];
    __shared__ uint32_t Bs[64][17];
    int t = threadIdx.x;
    int tx = t & 15, ty = t >> 4;
    int posBase = blockIdx.x * 64;
    int coBase  = blockIdx.y * 64;
    int r0 = t >> 4, c0 = t & 15;

    int acc[4][4];
#pragma unroll
    for (int i = 0; i < 4; i++)
#pragma unroll
        for (int j = 0; j < 4; j++) acc[i][j] = 0;

    for (int kc = 0; kc < 16; kc++) {
#pragma unroll
        for (int l = 0; l < 4; l++) {
            int r = r0 + l * 16;
            As[r][c0] = g_x8[(size_t)(posBase + r) * 256 + kc * 16 + c0];
            Bs[r][c0] = g_w1[(size_t)(coBase + r) * 256 + kc * 16 + c0];
        }
        __syncthreads();
#pragma unroll
        for (int c = 0; c < 16; c++) {
            uint32_t ar[4], br[4];
#pragma unroll
            for (int i = 0; i < 4; i++) ar[i] = As[ty * 4 + i][c];
#pragma unroll
            for (int j = 0; j < 4; j++) br[j] = Bs[tx * 4 + j][c];
#pragma unroll
            for (int i = 0; i < 4; i++)
#pragma unroll
                for (int j = 0; j < 4; j++)
                    acc[i][j] = __dp4a((int)ar[i], (int)br[j], acc[i][j]);
        }
        __syncthreads();
    }

    float av[4], bv[4], qv[4];
#pragma unroll
    for (int j = 0; j < 4; j++) {
        int co = coBase + tx * 4 + j;
        av[j] = alpha[co]; bv[j] = beta[co];
        qv[j] = exp2f((float)(q[co] + 12));
    }
#pragma unroll
    for (int i = 0; i < 4; i++) {
        int pos = posBase + ty * 4 + i;
        int v[4];
#pragma unroll
        for (int j = 0; j < 4; j++) v[j] = bn_clip_relu(acc[i][j], av[j], bv[j], qv[j]);
        g_a1[(size_t)pos * 64 + (coBase >> 2) + tx] = pack4(v[0], v[1], v[2], v[3]);
    }
}

// -------------------- conv2: 3x3 pad 1 as 9 shifted GEMM taps --------------------
__global__ void __launch_bounds__(256) conv2_kernel(const float* __restrict__ alpha,
                                                    const float* __restrict__ beta,
                                                    const int* __restrict__ q) {
    __shared__ uint32_t As[64][17];
    __shared__ uint32_t Bs[64][17];
    int t = threadIdx.x;
    int tx = t & 15, ty = t >> 4;
    int posBase = blockIdx.x * 64;
    int coBase  = blockIdx.y * 64;
    int r0 = t >> 4, c0 = t & 15;

    int acc[4][4];
#pragma unroll
    for (int i = 0; i < 4; i++)
#pragma unroll
        for (int j = 0; j < 4; j++) acc[i][j] = 0;

    // decompose the 4 A-load rows this thread owns
    int nimg[4], yy[4], xx[4];
#pragma unroll
    for (int l = 0; l < 4; l++) {
        int p = posBase + r0 + l * 16;
        int n = p / PIX;
        int rem = p - n * PIX;
        int y = rem / 28;
        nimg[l] = n; yy[l] = y; xx[l] = rem - y * 28;
    }

    for (int tap = 0; tap < 9; tap++) {
        int dy = tap / 3 - 1;
        int dx = tap - (tap / 3) * 3 - 1;
        int srcRow[4];
#pragma unroll
        for (int l = 0; l < 4; l++) {
            int ys = yy[l] + dy, xs = xx[l] + dx;
            srcRow[l] = (ys >= 0 && ys < 28 && xs >= 0 && xs < 28)
                            ? (nimg[l] * PIX + ys * 28 + xs) : -1;
        }
        for (int kc = 0; kc < 4; kc++) {
#pragma unroll
            for (int l = 0; l < 4; l++) {
                int r = r0 + l * 16;
                As[r][c0] = (srcRow[l] >= 0)
                                ? g_a1[(size_t)srcRow[l] * 64 + kc * 16 + c0] : 0u;
                Bs[r][c0] = g_w2[(size_t)(coBase + r) * 576 + tap * 64 + kc * 16 + c0];
            }
            __syncthreads();
#pragma unroll
            for (int c = 0; c < 16; c++) {
                uint32_t ar[4], br[4];
#pragma unroll
                for (int i = 0; i < 4; i++) ar[i] = As[ty * 4 + i][c];
#pragma unroll
                for (int j = 0; j < 4; j++) br[j] = Bs[tx * 4 + j][c];
#pragma unroll
                for (int i = 0; i < 4; i++)
#pragma unroll
                    for (int j = 0; j < 4; j++)
                        acc[i][j] = __dp4a((int)ar[i], (int)br[j], acc[i][j]);
            }
            __syncthreads();
        }
    }

    float av[4], bv[4], qv[4];
#pragma unroll
    for (int j = 0; j < 4; j++) {
        int co = coBase + tx * 4 + j;
        av[j] = alpha[co]; bv[j] = beta[co];
        qv[j] = exp2f((float)(q[co] + 12));
    }
#pragma unroll
    for (int i = 0; i < 4; i++) {
        int pos = posBase + ty * 4 + i;
        int v[4];
#pragma unroll
        for (int j = 0; j < 4; j++) v[j] = bn_clip_relu(acc[i][j], av[j], bv[j], qv[j]);
        g_a2[(size_t)pos * 64 + (coBase >> 2) + tx] = pack4(v[0], v[1], v[2], v[3]);
    }
}

// -------------------- conv3: 1x1 K=256 + BN + residual + clip/relu, NCHW out --------------------
__global__ void __launch_bounds__(256) conv3_kernel(const int* __restrict__ x,
                                                    const float* __restrict__ alpha,
                                                    const float* __restrict__ beta,
                                                    const int* __restrict__ q,
                                                    float* __restrict__ out) {
    __shared__ uint32_t As[64][17];
    __shared__ uint32_t Bs[64][17];
    int t = threadIdx.x;
    int tx = t & 15, ty = t >> 4;
    int posBase = blockIdx.x * 64;
    int coBase  = blockIdx.y * 64;
    int r0 = t >> 4, c0 = t & 15;

    int acc[4][4];
#pragma unroll
    for (int i = 0; i < 4; i++)
#pragma unroll
        for (int j = 0; j < 4; j++) acc[i][j] = 0;

    for (int kc = 0; kc < 4; kc++) {
#pragma unroll
        for (int l = 0; l < 4; l++) {
            int r = r0 + l * 16;
            As[r][c0] = g_a2[(size_t)(posBase + r) * 64 + kc * 16 + c0];
            Bs[r][c0] = g_w3[(size_t)(coBase + r) * 64 + kc * 16 + c0];
        }
        __syncthreads();
#pragma unroll
        for (int c = 0; c < 16; c++) {
            uint32_t ar[4], br[4];
#pragma unroll
            for (int i = 0; i < 4; i++) ar[i] = As[ty * 4 + i][c];
#pragma unroll
            for (int j = 0; j < 4; j++) br[j] = Bs[tx * 4 + j][c];
#pragma unroll
            for (int i = 0; i < 4; i++)
#pragma unroll
                for (int j = 0; j < 4; j++)
                    acc[i][j] = __dp4a((int)ar[i], (int)br[j], acc[i][j]);
        }
        __syncthreads();
    }

    // epilogue: bn3 + clip, + identity, clip + relu, write NCHW float4
    int pos0 = posBase + ty * 4;        // 4 consecutive positions, same image (784 % 4 == 0)
    int n = pos0 / PIX;
    int rem = pos0 - n * PIX;
#pragma unroll
    for (int j = 0; j < 4; j++) {
        int co = coBase + tx * 4 + j;
        float a = alpha[co], b = beta[co];
        float qq = exp2f((float)(q[co] + 12));
        size_t base = ((size_t)n * COUT + co) * PIX + rem;
        int4 id4 = *(const int4*)(x + base);
        float4 o;
        float v, sum;
        v = bn_clip(acc[0][j], a, b, qq); sum = v + (float)id4.x; o.x = fminf(fmaxf(sum, 0.0f), 127.0f);
        v = bn_clip(acc[1][j], a, b, qq); sum = v + (float)id4.y; o.y = fminf(fmaxf(sum, 0.0f), 127.0f);
        v = bn_clip(acc[2][j], a, b, qq); sum = v + (float)id4.z; o.z = fminf(fmaxf(sum, 0.0f), 127.0f);
        v = bn_clip(acc[3][j], a, b, qq); sum = v + (float)id4.w; o.w = fminf(fmaxf(sum, 0.0f), 127.0f);
        *(float4*)(out + base) = o;
    }
}

// -------------------- launch --------------------
extern "C" void kernel_launch(void* const* d_in, const int* in_sizes, int n_in,
                              void* d_out, int out_size) {
    const int*   x    = (const int*)d_in[0];
    const float* w21  = (const float*)d_in[1];
    const int*   s1   = (const int*)d_in[2];
    const float* w22  = (const float*)d_in[3];
    const int*   s2   = (const int*)d_in[4];
    const float* w23  = (const float*)d_in[5];
    const int*   s3   = (const int*)d_in[6];
    const float* al1  = (const float*)d_in[7];
    const float* be1  = (const float*)d_in[8];
    const int*   q1   = (const int*)d_in[9];
    const float* al2  = (const float*)d_in[10];
    const float* be2  = (const float*)d_in[11];
    const int*   q2   = (const int*)d_in[12];
    const float* al3  = (const float*)d_in[13];
    const float* be3  = (const float*)d_in[14];
    const int*   q3   = (const int*)d_in[15];
    float* out = (float*)d_out;

    pack_w1_kernel<<<256, 256>>>(w21, s1);
    pack_w2_kernel<<<576, 256>>>(w22, s2);
    pack_w3_kernel<<<256, 256>>>(w23, s3);
    xpose_kernel<<<dim3(25, 8, 16), 256>>>(x);

    conv1_kernel<<<dim3(196, 4), 256>>>(al1, be1, q1);
    conv2_kernel<<<dim3(196, 4), 256>>>(al2, be2, q2);
    conv3_kernel<<<dim3(196, 16), 256>>>(x, al3, be3, q3, out);
}

// round 3
// speedup vs baseline: 2.5455x; 2.5455x over previous
#include <cuda_runtime.h>
#include <cstdint>

#define NB    16
#define PIX   784
#define NPOS  12544
#define CIN   1024
#define WIDTH 256
#define COUT  1024

// -------- device scratch --------
__device__ uint32_t g_x8[NPOS * CIN / 4];          // x NHWC int8 (1024 B/pos)
__device__ uint32_t g_w1[WIDTH * CIN / 4];         // [co][ci]
__device__ uint32_t g_w2[WIDTH * 9 * WIDTH / 4];   // [co][tap][ci]
__device__ uint32_t g_w3[COUT * WIDTH / 4];        // [co][ci]
__device__ uint32_t g_a1[NPOS * WIDTH / 4];        // act1 NHWC int8 (256 B/pos)
__device__ uint32_t g_a2[NPOS * WIDTH / 4];        // act2 NHWC int8

static __device__ __forceinline__ uint32_t pack4(int v0, int v1, int v2, int v3) {
    return (uint32_t)(uint8_t)(int8_t)v0 |
           ((uint32_t)(uint8_t)(int8_t)v1 << 8) |
           ((uint32_t)(uint8_t)(int8_t)v2 << 16) |
           ((uint32_t)(uint8_t)(int8_t)v3 << 24);
}

static __device__ __forceinline__ int bn_clip_relu(int acc, float a, float b, float qq) {
    float t = __fadd_rn(__fmul_rn(a, (float)acc), __fmul_rn(b, qq));
    float r = rintf(t * (1.0f / 4096.0f));
    r = fminf(fmaxf(r, -128.0f), 127.0f);
    return (int)fmaxf(r, 0.0f);
}
static __device__ __forceinline__ float bn_clip(int acc, float a, float b, float qq) {
    float t = __fadd_rn(__fmul_rn(a, (float)acc), __fmul_rn(b, qq));
    float r = rintf(t * (1.0f / 4096.0f));
    return fminf(fmaxf(r, -128.0f), 127.0f);
}

__device__ __forceinline__ uint32_t smem_u32(const void* p) {
    uint32_t a;
    asm("{ .reg .u64 t; cvta.to.shared.u64 t, %1; cvt.u32.u64 %0, t; }" : "=r"(a) : "l"(p));
    return a;
}

// -------------------- weight packing (unchanged from R1, exact) --------------------
__global__ void pack_w1_kernel(const float* __restrict__ w, const int* __restrict__ s) {
    int wi = blockIdx.x * blockDim.x + threadIdx.x;
    if (wi >= WIDTH * CIN / 4) return;
    int v[4];
#pragma unroll
    for (int j = 0; j < 4; j++) { int idx = wi * 4 + j; v[j] = (int)w[idx] * (1 << s[idx]); }
    g_w1[wi] = pack4(v[0], v[1], v[2], v[3]);
}
__global__ void pack_w3_kernel(const float* __restrict__ w, const int* __restrict__ s) {
    int wi = blockIdx.x * blockDim.x + threadIdx.x;
    if (wi >= COUT * WIDTH / 4) return;
    int v[4];
#pragma unroll
    for (int j = 0; j < 4; j++) { int idx = wi * 4 + j; v[j] = (int)w[idx] * (1 << s[idx]); }
    g_w3[wi] = pack4(v[0], v[1], v[2], v[3]);
}
__global__ void pack_w2_kernel(const float* __restrict__ w, const int* __restrict__ s) {
    int wi = blockIdx.x * blockDim.x + threadIdx.x;
    if (wi >= WIDTH * 9 * WIDTH / 4) return;
    int co  = wi / 576;
    int rr  = wi - co * 576;
    int tap = rr >> 6;
    int cw  = rr & 63;
    int v[4];
#pragma unroll
    for (int j = 0; j < 4; j++) {
        int ci  = cw * 4 + j;
        int src = co * 2304 + ci * 9 + tap;
        v[j] = (int)w[src] * (1 << s[src]);
    }
    g_w2[wi] = pack4(v[0], v[1], v[2], v[3]);
}

// -------------------- NCHW int32 -> NHWC int8 transpose (R1) --------------------
__global__ void xpose_kernel(const int* __restrict__ x) {
    __shared__ uint32_t s[32][33];
    int t = threadIdx.x, bx = blockIdx.x, by = blockIdx.y, n = blockIdx.z;
    int phw_l = t & 31, phw = bx * 32 + phw_l;
#pragma unroll
    for (int l = 0; l < 4; l++) {
        int cwl = (t >> 5) + l * 8;
        uint32_t wv = 0;
        if (phw < PIX) {
            int ci = by * 128 + cwl * 4;
            const int* p = x + ((size_t)n * CIN + ci) * PIX + phw;
            wv = pack4(p[0], p[PIX], p[2 * PIX], p[3 * PIX]);
        }
        s[phw_l][cwl] = wv;
    }
    __syncthreads();
    int cwl2 = t & 31;
#pragma unroll
    for (int l = 0; l < 4; l++) {
        int pl = (t >> 5) + l * 8;
        int phw2 = bx * 32 + pl;
        if (phw2 < PIX)
            g_x8[((size_t)(n * PIX + phw2)) * 256 + by * 32 + cwl2] = s[pl][cwl2];
    }
}

// -------------------- IMMA tile machinery --------------------
// SMEM tiles: 128 rows x 64 bytes (K-chunk) padded to 80-byte row stride, double buffered.
#define RS   80
#define BUFB (128 * RS)

__device__ __forceinline__ void compute_chunk(uint32_t saBuf, uint32_t sbBuf,
                                              int m0, int n0, int lane,
                                              int acc[4][4][4]) {
#pragma unroll
    for (int ks = 0; ks < 2; ks++) {
        uint32_t af[4][4];
        uint32_t bf[4][2];
#pragma unroll
        for (int mi = 0; mi < 4; mi++) {
            uint32_t addr = saBuf + (uint32_t)((m0 + mi * 16 + (lane & 15)) * RS + ks * 32 + ((lane >> 4) << 4));
            asm volatile("ldmatrix.sync.aligned.m8n8.x4.shared.b16 {%0,%1,%2,%3}, [%4];"
                         : "=r"(af[mi][0]), "=r"(af[mi][1]), "=r"(af[mi][2]), "=r"(af[mi][3])
                         : "r"(addr));
        }
#pragma unroll
        for (int np = 0; np < 2; np++) {
            int rowb = n0 + np * 16 + ((lane >> 4) << 3) + (lane & 7);
            uint32_t addr = sbBuf + (uint32_t)(rowb * RS + ks * 32 + (((lane >> 3) & 1) << 4));
            asm volatile("ldmatrix.sync.aligned.m8n8.x4.shared.b16 {%0,%1,%2,%3}, [%4];"
                         : "=r"(bf[np * 2][0]), "=r"(bf[np * 2][1]),
                           "=r"(bf[np * 2 + 1][0]), "=r"(bf[np * 2 + 1][1])
                         : "r"(addr));
        }
#pragma unroll
        for (int mi = 0; mi < 4; mi++)
#pragma unroll
            for (int ni = 0; ni < 4; ni++)
                asm volatile("mma.sync.aligned.m16n8k32.row.col.s32.s8.s8.s32 "
                             "{%0,%1,%2,%3}, {%4,%5,%6,%7}, {%8,%9}, {%0,%1,%2,%3};"
                             : "+r"(acc[mi][ni][0]), "+r"(acc[mi][ni][1]),
                               "+r"(acc[mi][ni][2]), "+r"(acc[mi][ni][3])
                             : "r"(af[mi][0]), "r"(af[mi][1]), "r"(af[mi][2]), "r"(af[mi][3]),
                               "r"(bf[ni][0]), "r"(bf[ni][1]));
    }
}

// epilogue for conv1/conv2: BN+clip+relu, pack int8 pairs, NHWC store
__device__ __forceinline__ void epi_act(int acc[4][4][4], int posBase, int coBase,
                                        int m0, int n0, int lane,
                                        const float* __restrict__ alpha,
                                        const float* __restrict__ beta,
                                        const int* __restrict__ q,
                                        uint32_t* __restrict__ dstw) {
    int8_t* dst = (int8_t*)dstw;
#pragma unroll
    for (int ni = 0; ni < 4; ni++) {
        int co0 = coBase + n0 + ni * 8 + (lane & 3) * 2;
        float a0 = alpha[co0], a1 = alpha[co0 + 1];
        float b0 = beta[co0],  b1 = beta[co0 + 1];
        float q0 = exp2f((float)(q[co0] + 12)), q1 = exp2f((float)(q[co0 + 1] + 12));
        int coL = (co0 - coBase) + coBase;   // global channel within WIDTH row
#pragma unroll
        for (int mi = 0; mi < 4; mi++) {
            int p0 = posBase + m0 + mi * 16 + (lane >> 2);
            int v0 = bn_clip_relu(acc[mi][ni][0], a0, b0, q0);
            int v1 = bn_clip_relu(acc[mi][ni][1], a1, b1, q1);
            *(uint16_t*)(dst + (size_t)p0 * WIDTH + coL) =
                (uint16_t)((v0 & 0xFF) | (v1 << 8));
            int v2 = bn_clip_relu(acc[mi][ni][2], a0, b0, q0);
            int v3 = bn_clip_relu(acc[mi][ni][3], a1, b1, q1);
            *(uint16_t*)(dst + (size_t)(p0 + 8) * WIDTH + coL) =
                (uint16_t)((v2 & 0xFF) | (v3 << 8));
        }
    }
}

// -------------------- conv1: K=1024 (16 chunks), N=256 --------------------
__global__ void __launch_bounds__(256) conv1_imma(const float* __restrict__ alpha,
                                                  const float* __restrict__ beta,
                                                  const int* __restrict__ q) {
    __shared__ int8_t sA[2 * BUFB];
    __shared__ int8_t sB[2 * BUFB];
    int t = threadIdx.x, lane = t & 31, wid = t >> 5;
    int m0 = (wid >> 2) * 64, n0 = (wid & 3) * 32;
    int posBase = blockIdx.x * 128, coBase = blockIdx.y * 128;
    uint32_t sa32 = smem_u32(sA), sb32 = smem_u32(sB);
    const int8_t* gx = (const int8_t*)g_x8;
    const int8_t* gw = (const int8_t*)g_w1;

    int acc[4][4][4];
#pragma unroll
    for (int i = 0; i < 4; i++)
#pragma unroll
        for (int j = 0; j < 4; j++)
#pragma unroll
            for (int k = 0; k < 4; k++) acc[i][j][k] = 0;

    int row = t >> 1, off = (t & 1) * 32;
    auto load = [&](int ch) {
        int b = ch & 1;
        const int8_t* ga = gx + (size_t)(posBase + row) * CIN + ch * 64 + off;
        *(uint4*)&sA[b * BUFB + row * RS + off]      = *(const uint4*)ga;
        *(uint4*)&sA[b * BUFB + row * RS + off + 16] = *(const uint4*)(ga + 16);
        const int8_t* gb = gw + (size_t)(coBase + row) * CIN + ch * 64 + off;
        *(uint4*)&sB[b * BUFB + row * RS + off]      = *(const uint4*)gb;
        *(uint4*)&sB[b * BUFB + row * RS + off + 16] = *(const uint4*)(gb + 16);
    };

    load(0);
    for (int ch = 0; ch < 16; ch++) {
        __syncthreads();
        if (ch + 1 < 16) load(ch + 1);
        compute_chunk(sa32 + (ch & 1) * BUFB, sb32 + (ch & 1) * BUFB, m0, n0, lane, acc);
    }
    epi_act(acc, posBase, coBase, m0, n0, lane, alpha, beta, q, g_a1);
}

// -------------------- conv2: 9 taps x 4 chunks = 36, N=256 --------------------
__global__ void __launch_bounds__(256) conv2_imma(const float* __restrict__ alpha,
                                                  const float* __restrict__ beta,
                                                  const int* __restrict__ q) {
    __shared__ int8_t sA[2 * BUFB];
    __shared__ int8_t sB[2 * BUFB];
    int t = threadIdx.x, lane = t & 31, wid = t >> 5;
    int m0 = (wid >> 2) * 64, n0 = (wid & 3) * 32;
    int posBase = blockIdx.x * 128, coBase = blockIdx.y * 128;
    uint32_t sa32 = smem_u32(sA), sb32 = smem_u32(sB);
    const int8_t* ga1 = (const int8_t*)g_a1;
    const int8_t* gw = (const int8_t*)g_w2;

    int acc[4][4][4];
#pragma unroll
    for (int i = 0; i < 4; i++)
#pragma unroll
        for (int j = 0; j < 4; j++)
#pragma unroll
            for (int k = 0; k < 4; k++) acc[i][j][k] = 0;

    int row = t >> 1, off = (t & 1) * 32;
    int pos = posBase + row;
    int pimg = pos / PIX, prem = pos - pimg * PIX;
    int py = prem / 28, px = prem - py * 28;

    auto load = [&](int ch) {
        int b = ch & 1;
        int tap = ch >> 2, kc = ch & 3;
        int dy = tap / 3 - 1, dx = tap - (tap / 3) * 3 - 1;
        int ys = py + dy, xs = px + dx;
        uint4 va0 = make_uint4(0, 0, 0, 0), va1 = make_uint4(0, 0, 0, 0);
        if (ys >= 0 && ys < 28 && xs >= 0 && xs < 28) {
            const int8_t* ga = ga1 + ((size_t)(pimg * PIX + ys * 28 + xs) * WIDTH) + kc * 64 + off;
            va0 = *(const uint4*)ga;
            va1 = *(const uint4*)(ga + 16);
        }
        *(uint4*)&sA[b * BUFB + row * RS + off]      = va0;
        *(uint4*)&sA[b * BUFB + row * RS + off + 16] = va1;
        const int8_t* gb = gw + (size_t)(coBase + row) * 2304 + ch * 64 + off;
        *(uint4*)&sB[b * BUFB + row * RS + off]      = *(const uint4*)gb;
        *(uint4*)&sB[b * BUFB + row * RS + off + 16] = *(const uint4*)(gb + 16);
    };

    load(0);
    for (int ch = 0; ch < 36; ch++) {
        __syncthreads();
        if (ch + 1 < 36) load(ch + 1);
        compute_chunk(sa32 + (ch & 1) * BUFB, sb32 + (ch & 1) * BUFB, m0, n0, lane, acc);
    }
    epi_act(acc, posBase, coBase, m0, n0, lane, alpha, beta, q, g_a2);
}

// -------------------- conv3: K=256 (4 chunks), N=1024, + residual --------------------
__global__ void __launch_bounds__(256) conv3_imma(const int* __restrict__ x,
                                                  const float* __restrict__ alpha,
                                                  const float* __restrict__ beta,
                                                  const int* __restrict__ q,
                                                  float* __restrict__ out) {
    __shared__ int8_t sA[2 * BUFB];
    __shared__ int8_t sB[2 * BUFB];
    int t = threadIdx.x, lane = t & 31, wid = t >> 5;
    int m0 = (wid >> 2) * 64, n0 = (wid & 3) * 32;
    int posBase = blockIdx.x * 128, coBase = blockIdx.y * 128;
    uint32_t sa32 = smem_u32(sA), sb32 = smem_u32(sB);
    const int8_t* ga2 = (const int8_t*)g_a2;
    const int8_t* gw = (const int8_t*)g_w3;

    int acc[4][4][4];
#pragma unroll
    for (int i = 0; i < 4; i++)
#pragma unroll
        for (int j = 0; j < 4; j++)
#pragma unroll
            for (int k = 0; k < 4; k++) acc[i][j][k] = 0;

    int row = t >> 1, off = (t & 1) * 32;
    auto load = [&](int ch) {
        int b = ch & 1;
        const int8_t* ga = ga2 + (size_t)(posBase + row) * WIDTH + ch * 64 + off;
        *(uint4*)&sA[b * BUFB + row * RS + off]      = *(const uint4*)ga;
        *(uint4*)&sA[b * BUFB + row * RS + off + 16] = *(const uint4*)(ga + 16);
        const int8_t* gb = gw + (size_t)(coBase + row) * WIDTH + ch * 64 + off;
        *(uint4*)&sB[b * BUFB + row * RS + off]      = *(const uint4*)gb;
        *(uint4*)&sB[b * BUFB + row * RS + off + 16] = *(const uint4*)(gb + 16);
    };

    load(0);
    for (int ch = 0; ch < 4; ch++) {
        __syncthreads();
        if (ch + 1 < 4) load(ch + 1);
        compute_chunk(sa32 + (ch & 1) * BUFB, sb32 + (ch & 1) * BUFB, m0, n0, lane, acc);
    }

#pragma unroll
    for (int ni = 0; ni < 4; ni++) {
        int co0 = coBase + n0 + ni * 8 + (lane & 3) * 2;
        float a0 = alpha[co0], a1 = alpha[co0 + 1];
        float b0 = beta[co0],  b1 = beta[co0 + 1];
        float q0 = exp2f((float)(q[co0] + 12)), q1 = exp2f((float)(q[co0 + 1] + 12));
#pragma unroll
        for (int mi = 0; mi < 4; mi++) {
            int p0 = posBase + m0 + mi * 16 + (lane >> 2);
#pragma unroll
            for (int half = 0; half < 2; half++) {
                int p = p0 + half * 8;
                int n = p / PIX, rem = p - n * PIX;
                size_t gi0 = ((size_t)n * COUT + co0) * PIX + rem;
                size_t gi1 = gi0 + PIX;
                float v0 = bn_clip(acc[mi][ni][half * 2],     a0, b0, q0);
                float v1 = bn_clip(acc[mi][ni][half * 2 + 1], a1, b1, q1);
                float s0 = v0 + (float)x[gi0];
                float s1 = v1 + (float)x[gi1];
                out[gi0] = fminf(fmaxf(s0, 0.0f), 127.0f);
                out[gi1] = fminf(fmaxf(s1, 0.0f), 127.0f);
            }
        }
    }
}

// -------------------- launch --------------------
extern "C" void kernel_launch(void* const* d_in, const int* in_sizes, int n_in,
                              void* d_out, int out_size) {
    const int*   x   = (const int*)d_in[0];
    const float* w21 = (const float*)d_in[1];
    const int*   s1  = (const int*)d_in[2];
    const float* w22 = (const float*)d_in[3];
    const int*   s2  = (const int*)d_in[4];
    const float* w23 = (const float*)d_in[5];
    const int*   s3  = (const int*)d_in[6];
    const float* al1 = (const float*)d_in[7];
    const float* be1 = (const float*)d_in[8];
    const int*   q1  = (const int*)d_in[9];
    const float* al2 = (const float*)d_in[10];
    const float* be2 = (const float*)d_in[11];
    const int*   q2  = (const int*)d_in[12];
    const float* al3 = (const float*)d_in[13];
    const float* be3 = (const float*)d_in[14];
    const int*   q3  = (const int*)d_in[15];
    float* out = (float*)d_out;

    pack_w1_kernel<<<256, 256>>>(w21, s1);
    pack_w2_kernel<<<576, 256>>>(w22, s2);
    pack_w3_kernel<<<256, 256>>>(w23, s3);
    xpose_kernel<<<dim3(25, 8, 16), 256>>>(x);

    conv1_imma<<<dim3(98, 2), 256>>>(al1, be1, q1);
    conv2_imma<<<dim3(98, 2), 256>>>(al2, be2, q2);
    conv3_imma<<<dim3(98, 8), 256>>>(x, al3, be3, q3, out);
}

// round 4
// speedup vs baseline: 3.0565x; 1.2007x over previous
#include <cuda_runtime.h>
#include <cstdint>

#define NB    16
#define PIX   784
#define NPOS  12544
#define CIN   1024
#define WIDTH 256
#define COUT  1024

// -------- device scratch --------
__device__ uint32_t g_x8[NPOS * CIN / 4];          // x NHWC int8 (1024 B/pos)
__device__ uint32_t g_w1[WIDTH * CIN / 4];         // [co][ci]
__device__ uint32_t g_w2[WIDTH * 9 * WIDTH / 4];   // [co][tap][ci]
__device__ uint32_t g_w3[COUT * WIDTH / 4];        // [co][ci]
__device__ uint32_t g_a1[NPOS * WIDTH / 4];        // act1 NHWC int8 (256 B/pos)
__device__ uint32_t g_a2[NPOS * WIDTH / 4];        // act2 NHWC int8

static __device__ __forceinline__ uint32_t pack4(int v0, int v1, int v2, int v3) {
    return (uint32_t)(uint8_t)(int8_t)v0 |
           ((uint32_t)(uint8_t)(int8_t)v1 << 8) |
           ((uint32_t)(uint8_t)(int8_t)v2 << 16) |
           ((uint32_t)(uint8_t)(int8_t)v3 << 24);
}

static __device__ __forceinline__ int bn_clip_relu(int acc, float a, float b, float qq) {
    float t = __fadd_rn(__fmul_rn(a, (float)acc), __fmul_rn(b, qq));
    float r = rintf(t * (1.0f / 4096.0f));
    r = fminf(fmaxf(r, -128.0f), 127.0f);
    return (int)fmaxf(r, 0.0f);
}
static __device__ __forceinline__ float bn_clip(int acc, float a, float b, float qq) {
    float t = __fadd_rn(__fmul_rn(a, (float)acc), __fmul_rn(b, qq));
    float r = rintf(t * (1.0f / 4096.0f));
    return fminf(fmaxf(r, -128.0f), 127.0f);
}

__device__ __forceinline__ uint32_t smem_u32(const void* p) {
    uint32_t a;
    asm("{ .reg .u64 t; cvta.to.shared.u64 t, %1; cvt.u32.u64 %0, t; }" : "=r"(a) : "l"(p));
    return a;
}

// cp.async helpers
#define CP16(dst, src)        asm volatile("cp.async.cg.shared.global [%0], [%1], 16;" :: "r"(dst), "l"(src))
#define CP16Z(dst, src, pred) asm volatile("cp.async.cg.shared.global [%0], [%1], 16, %2;" :: "r"(dst), "l"(src), "r"((pred) ? 16 : 0))
#define CP_COMMIT()           asm volatile("cp.async.commit_group;" ::: "memory")
#define CP_WAIT2()            asm volatile("cp.async.wait_group 2;" ::: "memory")

// -------------------- fused weight packing --------------------
// word ranges: w1 [0,65536), w2 [65536, 213—), w3 tail
#define W1W (WIDTH * CIN / 4)          // 65536
#define W2W (WIDTH * 9 * WIDTH / 4)    // 147456
#define W3W (COUT * WIDTH / 4)         // 65536
__global__ void pack_all_kernel(const float* __restrict__ w1, const int* __restrict__ s1,
                                const float* __restrict__ w2, const int* __restrict__ s2,
                                const float* __restrict__ w3, const int* __restrict__ s3) {
    int wi = blockIdx.x * blockDim.x + threadIdx.x;
    if (wi < W1W) {
        int v[4];
#pragma unroll
        for (int j = 0; j < 4; j++) { int idx = wi * 4 + j; v[j] = (int)w1[idx] * (1 << s1[idx]); }
        g_w1[wi] = pack4(v[0], v[1], v[2], v[3]);
    } else if (wi < W1W + W2W) {
        int k = wi - W1W;
        int co  = k / 576;
        int rr  = k - co * 576;
        int tap = rr >> 6;
        int cw  = rr & 63;
        int v[4];
#pragma unroll
        for (int j = 0; j < 4; j++) {
            int ci  = cw * 4 + j;
            int src = co * 2304 + ci * 9 + tap;
            v[j] = (int)w2[src] * (1 << s2[src]);
        }
        g_w2[k] = pack4(v[0], v[1], v[2], v[3]);
    } else if (wi < W1W + W2W + W3W) {
        int k = wi - W1W - W2W;
        int v[4];
#pragma unroll
        for (int j = 0; j < 4; j++) { int idx = k * 4 + j; v[j] = (int)w3[idx] * (1 << s3[idx]); }
        g_w3[k] = pack4(v[0], v[1], v[2], v[3]);
    }
}

// -------------------- NCHW int32 -> NHWC int8 transpose --------------------
__global__ void xpose_kernel(const int* __restrict__ x) {
    __shared__ uint32_t s[32][33];
    int t = threadIdx.x, bx = blockIdx.x, by = blockIdx.y, n = blockIdx.z;
    int phw_l = t & 31, phw = bx * 32 + phw_l;
#pragma unroll
    for (int l = 0; l < 4; l++) {
        int cwl = (t >> 5) + l * 8;
        uint32_t wv = 0;
        if (phw < PIX) {
            int ci = by * 128 + cwl * 4;
            const int* p = x + ((size_t)n * CIN + ci) * PIX + phw;
            wv = pack4(p[0], p[PIX], p[2 * PIX], p[3 * PIX]);
        }
        s[phw_l][cwl] = wv;
    }
    __syncthreads();
    int cwl2 = t & 31;
#pragma unroll
    for (int l = 0; l < 4; l++) {
        int pl = (t >> 5) + l * 8;
        int phw2 = bx * 32 + pl;
        if (phw2 < PIX)
            g_x8[((size_t)(n * PIX + phw2)) * 256 + by * 32 + cwl2] = s[pl][cwl2];
    }
}

// -------------------- IMMA tile machinery --------------------
// SMEM stage: 128 rows x 64 bytes, padded to 80-byte row stride; 4 stages, A then B.
#define RS     80
#define BUFB   (128 * RS)
#define STAGES 4
#define SMEM_BYTES (2 * STAGES * BUFB)

__device__ __forceinline__ void compute_chunk(uint32_t saBuf, uint32_t sbBuf,
                                              int m0, int n0, int lane,
                                              int acc[4][4][4]) {
#pragma unroll
    for (int ks = 0; ks < 2; ks++) {
        uint32_t af[4][4];
        uint32_t bf[4][2];
#pragma unroll
        for (int mi = 0; mi < 4; mi++) {
            uint32_t addr = saBuf + (uint32_t)((m0 + mi * 16 + (lane & 15)) * RS + ks * 32 + ((lane >> 4) << 4));
            asm volatile("ldmatrix.sync.aligned.m8n8.x4.shared.b16 {%0,%1,%2,%3}, [%4];"
                         : "=r"(af[mi][0]), "=r"(af[mi][1]), "=r"(af[mi][2]), "=r"(af[mi][3])
                         : "r"(addr));
        }
#pragma unroll
        for (int np = 0; np < 2; np++) {
            int rowb = n0 + np * 16 + ((lane >> 4) << 3) + (lane & 7);
            uint32_t addr = sbBuf + (uint32_t)(rowb * RS + ks * 32 + (((lane >> 3) & 1) << 4));
            asm volatile("ldmatrix.sync.aligned.m8n8.x4.shared.b16 {%0,%1,%2,%3}, [%4];"
                         : "=r"(bf[np * 2][0]), "=r"(bf[np * 2][1]),
                           "=r"(bf[np * 2 + 1][0]), "=r"(bf[np * 2 + 1][1])
                         : "r"(addr));
        }
#pragma unroll
        for (int mi = 0; mi < 4; mi++)
#pragma unroll
            for (int ni = 0; ni < 4; ni++)
                asm volatile("mma.sync.aligned.m16n8k32.row.col.s32.s8.s8.s32 "
                             "{%0,%1,%2,%3}, {%4,%5,%6,%7}, {%8,%9}, {%0,%1,%2,%3};"
                             : "+r"(acc[mi][ni][0]), "+r"(acc[mi][ni][1]),
                               "+r"(acc[mi][ni][2]), "+r"(acc[mi][ni][3])
                             : "r"(af[mi][0]), "r"(af[mi][1]), "r"(af[mi][2]), "r"(af[mi][3]),
                               "r"(bf[ni][0]), "r"(bf[ni][1]));
    }
}

__device__ __forceinline__ void epi_act(int acc[4][4][4], int posBase, int coBase,
                                        int m0, int n0, int lane,
                                        const float* __restrict__ alpha,
                                        const float* __restrict__ beta,
                                        const int* __restrict__ q,
                                        uint32_t* __restrict__ dstw) {
    int8_t* dst = (int8_t*)dstw;
#pragma unroll
    for (int ni = 0; ni < 4; ni++) {
        int co0 = coBase + n0 + ni * 8 + (lane & 3) * 2;
        float a0 = alpha[co0], a1 = alpha[co0 + 1];
        float b0 = beta[co0],  b1 = beta[co0 + 1];
        float q0 = exp2f((float)(q[co0] + 12)), q1 = exp2f((float)(q[co0 + 1] + 12));
#pragma unroll
        for (int mi = 0; mi < 4; mi++) {
            int p0 = posBase + m0 + mi * 16 + (lane >> 2);
            int v0 = bn_clip_relu(acc[mi][ni][0], a0, b0, q0);
            int v1 = bn_clip_relu(acc[mi][ni][1], a1, b1, q1);
            *(uint16_t*)(dst + (size_t)p0 * WIDTH + co0) = (uint16_t)((v0 & 0xFF) | (v1 << 8));
            int v2 = bn_clip_relu(acc[mi][ni][2], a0, b0, q0);
            int v3 = bn_clip_relu(acc[mi][ni][3], a1, b1, q1);
            *(uint16_t*)(dst + (size_t)(p0 + 8) * WIDTH + co0) = (uint16_t)((v2 & 0xFF) | (v3 << 8));
        }
    }
}

// -------------------- conv1: K=1024 (16 chunks), N=256 --------------------
__global__ void __launch_bounds__(256) conv1_imma(const float* __restrict__ alpha,
                                                  const float* __restrict__ beta,
                                                  const int* __restrict__ q) {
    extern __shared__ int8_t smem[];
    int8_t* sA = smem;
    int8_t* sB = smem + STAGES * BUFB;
    int t = threadIdx.x, lane = t & 31, wid = t >> 5;
    int m0 = (wid >> 2) * 64, n0 = (wid & 3) * 32;
    int posBase = blockIdx.x * 128, coBase = blockIdx.y * 128;
    uint32_t sa32 = smem_u32(sA), sb32 = smem_u32(sB);
    const int8_t* gx = (const int8_t*)g_x8;
    const int8_t* gw = (const int8_t*)g_w1;

    int acc[4][4][4];
#pragma unroll
    for (int i = 0; i < 4; i++)
#pragma unroll
        for (int j = 0; j < 4; j++)
#pragma unroll
            for (int k = 0; k < 4; k++) acc[i][j][k] = 0;

    int row = t >> 1, off = (t & 1) * 32;
    uint32_t dA = sa32 + row * RS + off;
    uint32_t dB = sb32 + row * RS + off;
    const int8_t* gA = gx + (size_t)(posBase + row) * CIN + off;
    const int8_t* gB = gw + (size_t)(coBase + row) * CIN + off;

    auto load = [&](int ch) {
        uint32_t sO = (uint32_t)((ch & 3) * BUFB);
        CP16(dA + sO,      gA + ch * 64);
        CP16(dA + sO + 16, gA + ch * 64 + 16);
        CP16(dB + sO,      gB + ch * 64);
        CP16(dB + sO + 16, gB + ch * 64 + 16);
    };

    load(0); CP_COMMIT(); load(1); CP_COMMIT(); load(2); CP_COMMIT();
    const int NCH = 16;
    for (int ch = 0; ch < NCH; ch++) {
        CP_WAIT2();
        __syncthreads();
        compute_chunk(sa32 + (ch & 3) * BUFB, sb32 + (ch & 3) * BUFB, m0, n0, lane, acc);
        if (ch + 3 < NCH) load(ch + 3);
        CP_COMMIT();
    }
    epi_act(acc, posBase, coBase, m0, n0, lane, alpha, beta, q, g_a1);
}

// -------------------- conv2: 9 taps x 4 chunks = 36, N=256 --------------------
__global__ void __launch_bounds__(256) conv2_imma(const float* __restrict__ alpha,
                                                  const float* __restrict__ beta,
                                                  const int* __restrict__ q) {
    extern __shared__ int8_t smem[];
    int8_t* sA = smem;
    int8_t* sB = smem + STAGES * BUFB;
    int t = threadIdx.x, lane = t & 31, wid = t >> 5;
    int m0 = (wid >> 2) * 64, n0 = (wid & 3) * 32;
    int posBase = blockIdx.x * 128, coBase = blockIdx.y * 128;
    uint32_t sa32 = smem_u32(sA), sb32 = smem_u32(sB);
    const int8_t* ga1 = (const int8_t*)g_a1;
    const int8_t* gw = (const int8_t*)g_w2;

    int acc[4][4][4];
#pragma unroll
    for (int i = 0; i < 4; i++)
#pragma unroll
        for (int j = 0; j < 4; j++)
#pragma unroll
            for (int k = 0; k < 4; k++) acc[i][j][k] = 0;

    int row = t >> 1, off = (t & 1) * 32;
    uint32_t dA = sa32 + row * RS + off;
    uint32_t dB = sb32 + row * RS + off;
    int pos = posBase + row;
    int pimg = pos / PIX, prem = pos - pimg * PIX;
    int py = prem / 28, px = prem - py * 28;
    const int8_t* gB = gw + (size_t)(coBase + row) * 2304 + off;

    auto load = [&](int ch) {
        uint32_t sO = (uint32_t)((ch & 3) * BUFB);
        int tap = ch >> 2, kc = ch & 3;
        int dy = tap / 3 - 1, dx = tap - (tap / 3) * 3 - 1;
        int ys = py + dy, xs = px + dx;
        bool ok = (ys >= 0 && ys < 28 && xs >= 0 && xs < 28);
        const int8_t* gA = ga1 + ((size_t)(pimg * PIX + ys * 28 + xs) * WIDTH) + kc * 64 + off;
        CP16Z(dA + sO,      gA,      ok);
        CP16Z(dA + sO + 16, gA + 16, ok);
        CP16(dB + sO,      gB + ch * 64);
        CP16(dB + sO + 16, gB + ch * 64 + 16);
    };

    load(0); CP_COMMIT(); load(1); CP_COMMIT(); load(2); CP_COMMIT();
    const int NCH = 36;
    for (int ch = 0; ch < NCH; ch++) {
        CP_WAIT2();
        __syncthreads();
        compute_chunk(sa32 + (ch & 3) * BUFB, sb32 + (ch & 3) * BUFB, m0, n0, lane, acc);
        if (ch + 3 < NCH) load(ch + 3);
        CP_COMMIT();
    }
    epi_act(acc, posBase, coBase, m0, n0, lane, alpha, beta, q, g_a2);
}

// -------------------- conv3: K=256 (4 chunks), N=1024, + residual --------------------
__global__ void __launch_bounds__(256) conv3_imma(const int* __restrict__ x,
                                                  const float* __restrict__ alpha,
                                                  const float* __restrict__ beta,
                                                  const int* __restrict__ q,
                                                  float* __restrict__ out) {
    extern __shared__ int8_t smem[];
    int8_t* sA = smem;
    int8_t* sB = smem + STAGES * BUFB;
    int t = threadIdx.x, lane = t & 31, wid = t >> 5;
    int m0 = (wid >> 2) * 64, n0 = (wid & 3) * 32;
    int posBase = blockIdx.x * 128, coBase = blockIdx.y * 128;
    uint32_t sa32 = smem_u32(sA), sb32 = smem_u32(sB);
    const int8_t* ga2 = (const int8_t*)g_a2;
    const int8_t* gw = (const int8_t*)g_w3;

    int acc[4][4][4];
#pragma unroll
    for (int i = 0; i < 4; i++)
#pragma unroll
        for (int j = 0; j < 4; j++)
#pragma unroll
            for (int k = 0; k < 4; k++) acc[i][j][k] = 0;

    int row = t >> 1, off = (t & 1) * 32;
    uint32_t dA = sa32 + row * RS + off;
    uint32_t dB = sb32 + row * RS + off;
    const int8_t* gA = ga2 + (size_t)(posBase + row) * WIDTH + off;
    const int8_t* gB = gw + (size_t)(coBase + row) * WIDTH + off;

    auto load = [&](int ch) {
        uint32_t sO = (uint32_t)((ch & 3) * BUFB);
        CP16(dA + sO,      gA + ch * 64);
        CP16(dA + sO + 16, gA + ch * 64 + 16);
        CP16(dB + sO,      gB + ch * 64);
        CP16(dB + sO + 16, gB + ch * 64 + 16);
    };

    load(0); CP_COMMIT(); load(1); CP_COMMIT(); load(2); CP_COMMIT();
    const int NCH = 4;
    for (int ch = 0; ch < NCH; ch++) {
        CP_WAIT2();
        __syncthreads();
        compute_chunk(sa32 + (ch & 3) * BUFB, sb32 + (ch & 3) * BUFB, m0, n0, lane, acc);
        if (ch + 3 < NCH) load(ch + 3);
        CP_COMMIT();
    }

#pragma unroll
    for (int ni = 0; ni < 4; ni++) {
        int co0 = coBase + n0 + ni * 8 + (lane & 3) * 2;
        float a0 = alpha[co0], a1 = alpha[co0 + 1];
        float b0 = beta[co0],  b1 = beta[co0 + 1];
        float q0 = exp2f((float)(q[co0] + 12)), q1 = exp2f((float)(q[co0 + 1] + 12));
#pragma unroll
        for (int mi = 0; mi < 4; mi++) {
            int p0 = posBase + m0 + mi * 16 + (lane >> 2);
#pragma unroll
            for (int half = 0; half < 2; half++) {
                int p = p0 + half * 8;
                int n = p / PIX, rem = p - n * PIX;
                size_t gi0 = ((size_t)n * COUT + co0) * PIX + rem;
                size_t gi1 = gi0 + PIX;
                float v0 = bn_clip(acc[mi][ni][half * 2],     a0, b0, q0);
                float v1 = bn_clip(acc[mi][ni][half * 2 + 1], a1, b1, q1);
                float s0 = v0 + (float)x[gi0];
                float s1 = v1 + (float)x[gi1];
                out[gi0] = fminf(fmaxf(s0, 0.0f), 127.0f);
                out[gi1] = fminf(fmaxf(s1, 0.0f), 127.0f);
            }
        }
    }
}

// -------------------- launch --------------------
extern "C" void kernel_launch(void* const* d_in, const int* in_sizes, int n_in,
                              void* d_out, int out_size) {
    const int*   x   = (const int*)d_in[0];
    const float* w21 = (const float*)d_in[1];
    const int*   s1  = (const int*)d_in[2];
    const float* w22 = (const float*)d_in[3];
    const int*   s2  = (const int*)d_in[4];
    const float* w23 = (const float*)d_in[5];
    const int*   s3  = (const int*)d_in[6];
    const float* al1 = (const float*)d_in[7];
    const float* be1 = (const float*)d_in[8];
    const int*   q1  = (const int*)d_in[9];
    const float* al2 = (const float*)d_in[10];
    const float* be2 = (const float*)d_in[11];
    const int*   q2  = (const int*)d_in[12];
    const float* al3 = (const float*)d_in[13];
    const float* be3 = (const float*)d_in[14];
    const int*   q3  = (const int*)d_in[15];
    float* out = (float*)d_out;

    cudaFuncSetAttribute(conv1_imma, cudaFuncAttributeMaxDynamicSharedMemorySize, SMEM_BYTES);
    cudaFuncSetAttribute(conv2_imma, cudaFuncAttributeMaxDynamicSharedMemorySize, SMEM_BYTES);
    cudaFuncSetAttribute(conv3_imma, cudaFuncAttributeMaxDynamicSharedMemorySize, SMEM_BYTES);

    pack_all_kernel<<<(W1W + W2W + W3W + 255) / 256, 256>>>(w21, s1, w22, s2, w23, s3);
    xpose_kernel<<<dim3(25, 8, 16), 256>>>(x);

    conv1_imma<<<dim3(98, 2), 256, SMEM_BYTES>>>(al1, be1, q1);
    conv2_imma<<<dim3(98, 2), 256, SMEM_BYTES>>>(al2, be2, q2);
    conv3_imma<<<dim3(98, 8), 256, SMEM_BYTES>>>(x, al3, be3, q3, out);
}

// round 5
// speedup vs baseline: 3.1620x; 1.0345x over previous
#include <cuda_runtime.h>
#include <cstdint>

#define NB    16
#define PIX   784
#define NPOS  12544
#define CIN   1024
#define WIDTH 256
#define COUT  1024

// -------- device scratch --------
__device__ uint32_t g_x8[NPOS * CIN / 4];          // x NHWC int8 (1024 B/pos)
__device__ uint32_t g_w1[WIDTH * CIN / 4];         // [co][ci]
__device__ uint32_t g_w2[WIDTH * 9 * WIDTH / 4];   // [co][tap][ci]
__device__ uint32_t g_w3[COUT * WIDTH / 4];        // [co][ci]
__device__ uint32_t g_a1[NPOS * WIDTH / 4];        // act1 NHWC int8 (256 B/pos)
__device__ uint32_t g_a2[NPOS * WIDTH / 4];        // act2 NHWC int8

static __device__ __forceinline__ uint32_t pack4(int v0, int v1, int v2, int v3) {
    return (uint32_t)(uint8_t)(int8_t)v0 |
           ((uint32_t)(uint8_t)(int8_t)v1 << 8) |
           ((uint32_t)(uint8_t)(int8_t)v2 << 16) |
           ((uint32_t)(uint8_t)(int8_t)v3 << 24);
}

static __device__ __forceinline__ int bn_clip_relu(int acc, float a, float b, float qq) {
    float t = __fadd_rn(__fmul_rn(a, (float)acc), __fmul_rn(b, qq));
    float r = rintf(t * (1.0f / 4096.0f));
    r = fminf(fmaxf(r, -128.0f), 127.0f);
    return (int)fmaxf(r, 0.0f);
}
static __device__ __forceinline__ float bn_clip(int acc, float a, float b, float qq) {
    float t = __fadd_rn(__fmul_rn(a, (float)acc), __fmul_rn(b, qq));
    float r = rintf(t * (1.0f / 4096.0f));
    return fminf(fmaxf(r, -128.0f), 127.0f);
}

__device__ __forceinline__ uint32_t smem_u32(const void* p) {
    uint32_t a;
    asm("{ .reg .u64 t; cvta.to.shared.u64 t, %1; cvt.u32.u64 %0, t; }" : "=r"(a) : "l"(p));
    return a;
}

#define CP16(dst, src)        asm volatile("cp.async.cg.shared.global [%0], [%1], 16;" :: "r"(dst), "l"(src))
#define CP16Z(dst, src, pred) asm volatile("cp.async.cg.shared.global [%0], [%1], 16, %2;" :: "r"(dst), "l"(src), "r"((pred) ? 16 : 0))
#define CP_COMMIT()           asm volatile("cp.async.commit_group;" ::: "memory")
#define CP_WAIT2()            asm volatile("cp.async.wait_group 2;" ::: "memory")

// -------------------- fused weight packing --------------------
#define W1W (WIDTH * CIN / 4)
#define W2W (WIDTH * 9 * WIDTH / 4)
#define W3W (COUT * WIDTH / 4)
__global__ void pack_all_kernel(const float* __restrict__ w1, const int* __restrict__ s1,
                                const float* __restrict__ w2, const int* __restrict__ s2,
                                const float* __restrict__ w3, const int* __restrict__ s3) {
    int wi = blockIdx.x * blockDim.x + threadIdx.x;
    if (wi < W1W) {
        int v[4];
#pragma unroll
        for (int j = 0; j < 4; j++) { int idx = wi * 4 + j; v[j] = (int)w1[idx] * (1 << s1[idx]); }
        g_w1[wi] = pack4(v[0], v[1], v[2], v[3]);
    } else if (wi < W1W + W2W) {
        int k = wi - W1W;
        int co  = k / 576;
        int rr  = k - co * 576;
        int tap = rr >> 6;
        int cw  = rr & 63;
        int v[4];
#pragma unroll
        for (int j = 0; j < 4; j++) {
            int ci  = cw * 4 + j;
            int src = co * 2304 + ci * 9 + tap;
            v[j] = (int)w2[src] * (1 << s2[src]);
        }
        g_w2[k] = pack4(v[0], v[1], v[2], v[3]);
    } else if (wi < W1W + W2W + W3W) {
        int k = wi - W1W - W2W;
        int v[4];
#pragma unroll
        for (int j = 0; j < 4; j++) { int idx = k * 4 + j; v[j] = (int)w3[idx] * (1 << s3[idx]); }
        g_w3[k] = pack4(v[0], v[1], v[2], v[3]);
    }
}

// -------------------- NCHW int32 -> NHWC int8 transpose --------------------
__global__ void xpose_kernel(const int* __restrict__ x) {
    __shared__ uint32_t s[32][33];
    int t = threadIdx.x, bx = blockIdx.x, by = blockIdx.y, n = blockIdx.z;
    int phw_l = t & 31, phw = bx * 32 + phw_l;
#pragma unroll
    for (int l = 0; l < 4; l++) {
        int cwl = (t >> 5) + l * 8;
        uint32_t wv = 0;
        if (phw < PIX) {
            int ci = by * 128 + cwl * 4;
            const int* p = x + ((size_t)n * CIN + ci) * PIX + phw;
            wv = pack4(p[0], p[PIX], p[2 * PIX], p[3 * PIX]);
        }
        s[phw_l][cwl] = wv;
    }
    __syncthreads();
    int cwl2 = t & 31;
#pragma unroll
    for (int l = 0; l < 4; l++) {
        int pl = (t >> 5) + l * 8;
        int phw2 = bx * 32 + pl;
        if (phw2 < PIX)
            g_x8[((size_t)(n * PIX + phw2)) * 256 + by * 32 + cwl2] = s[pl][cwl2];
    }
}

// -------------------- IMMA tile machinery --------------------
#define RS      80
#define STAGES  4
#define ABUF    (64 * RS)          // conv1/2: 64-pos A stage
#define BBUF    (128 * RS)         // 128-row B stage (and conv3 A stage)
#define SMEM12  (STAGES * (ABUF + BBUF))   // 61440
#define SMEM3   (2 * STAGES * BBUF)        // 81920

// warp tile 32 pos x 32 co (conv1/2)
__device__ __forceinline__ void compute_chunk64(uint32_t saBuf, uint32_t sbBuf,
                                                int m0, int n0, int lane,
                                                int acc[2][4][4]) {
#pragma unroll
    for (int ks = 0; ks < 2; ks++) {
        uint32_t af[2][4];
        uint32_t bf[4][2];
#pragma unroll
        for (int mi = 0; mi < 2; mi++) {
            uint32_t addr = saBuf + (uint32_t)((m0 + mi * 16 + (lane & 15)) * RS + ks * 32 + ((lane >> 4) << 4));
            asm volatile("ldmatrix.sync.aligned.m8n8.x4.shared.b16 {%0,%1,%2,%3}, [%4];"
                         : "=r"(af[mi][0]), "=r"(af[mi][1]), "=r"(af[mi][2]), "=r"(af[mi][3])
                         : "r"(addr));
        }
#pragma unroll
        for (int np = 0; np < 2; np++) {
            int rowb = n0 + np * 16 + ((lane >> 4) << 3) + (lane & 7);
            uint32_t addr = sbBuf + (uint32_t)(rowb * RS + ks * 32 + (((lane >> 3) & 1) << 4));
            asm volatile("ldmatrix.sync.aligned.m8n8.x4.shared.b16 {%0,%1,%2,%3}, [%4];"
                         : "=r"(bf[np * 2][0]), "=r"(bf[np * 2][1]),
                           "=r"(bf[np * 2 + 1][0]), "=r"(bf[np * 2 + 1][1])
                         : "r"(addr));
        }
#pragma unroll
        for (int mi = 0; mi < 2; mi++)
#pragma unroll
            for (int ni = 0; ni < 4; ni++)
                asm volatile("mma.sync.aligned.m16n8k32.row.col.s32.s8.s8.s32 "
                             "{%0,%1,%2,%3}, {%4,%5,%6,%7}, {%8,%9}, {%0,%1,%2,%3};"
                             : "+r"(acc[mi][ni][0]), "+r"(acc[mi][ni][1]),
                               "+r"(acc[mi][ni][2]), "+r"(acc[mi][ni][3])
                             : "r"(af[mi][0]), "r"(af[mi][1]), "r"(af[mi][2]), "r"(af[mi][3]),
                               "r"(bf[ni][0]), "r"(bf[ni][1]));
    }
}

// warp tile 64 pos x 32 co (conv3)
__device__ __forceinline__ void compute_chunk128(uint32_t saBuf, uint32_t sbBuf,
                                                 int m0, int n0, int lane,
                                                 int acc[4][4][4]) {
#pragma unroll
    for (int ks = 0; ks < 2; ks++) {
        uint32_t af[4][4];
        uint32_t bf[4][2];
#pragma unroll
        for (int mi = 0; mi < 4; mi++) {
            uint32_t addr = saBuf + (uint32_t)((m0 + mi * 16 + (lane & 15)) * RS + ks * 32 + ((lane >> 4) << 4));
            asm volatile("ldmatrix.sync.aligned.m8n8.x4.shared.b16 {%0,%1,%2,%3}, [%4];"
                         : "=r"(af[mi][0]), "=r"(af[mi][1]), "=r"(af[mi][2]), "=r"(af[mi][3])
                         : "r"(addr));
        }
#pragma unroll
        for (int np = 0; np < 2; np++) {
            int rowb = n0 + np * 16 + ((lane >> 4) << 3) + (lane & 7);
            uint32_t addr = sbBuf + (uint32_t)(rowb * RS + ks * 32 + (((lane >> 3) & 1) << 4));
            asm volatile("ldmatrix.sync.aligned.m8n8.x4.shared.b16 {%0,%1,%2,%3}, [%4];"
                         : "=r"(bf[np * 2][0]), "=r"(bf[np * 2][1]),
                           "=r"(bf[np * 2 + 1][0]), "=r"(bf[np * 2 + 1][1])
                         : "r"(addr));
        }
#pragma unroll
        for (int mi = 0; mi < 4; mi++)
#pragma unroll
            for (int ni = 0; ni < 4; ni++)
                asm volatile("mma.sync.aligned.m16n8k32.row.col.s32.s8.s8.s32 "
                             "{%0,%1,%2,%3}, {%4,%5,%6,%7}, {%8,%9}, {%0,%1,%2,%3};"
                             : "+r"(acc[mi][ni][0]), "+r"(acc[mi][ni][1]),
                               "+r"(acc[mi][ni][2]), "+r"(acc[mi][ni][3])
                             : "r"(af[mi][0]), "r"(af[mi][1]), "r"(af[mi][2]), "r"(af[mi][3]),
                               "r"(bf[ni][0]), "r"(bf[ni][1]));
    }
}

__device__ __forceinline__ void epi_act64(int acc[2][4][4], int posBase, int coBase,
                                          int m0, int n0, int lane,
                                          const float* __restrict__ alpha,
                                          const float* __restrict__ beta,
                                          const int* __restrict__ q,
                                          uint32_t* __restrict__ dstw) {
    int8_t* dst = (int8_t*)dstw;
#pragma unroll
    for (int ni = 0; ni < 4; ni++) {
        int co0 = coBase + n0 + ni * 8 + (lane & 3) * 2;
        float a0 = alpha[co0], a1 = alpha[co0 + 1];
        float b0 = beta[co0],  b1 = beta[co0 + 1];
        float q0 = exp2f((float)(q[co0] + 12)), q1 = exp2f((float)(q[co0 + 1] + 12));
#pragma unroll
        for (int mi = 0; mi < 2; mi++) {
            int p0 = posBase + m0 + mi * 16 + (lane >> 2);
            int v0 = bn_clip_relu(acc[mi][ni][0], a0, b0, q0);
            int v1 = bn_clip_relu(acc[mi][ni][1], a1, b1, q1);
            *(uint16_t*)(dst + (size_t)p0 * WIDTH + co0) = (uint16_t)((v0 & 0xFF) | (v1 << 8));
            int v2 = bn_clip_relu(acc[mi][ni][2], a0, b0, q0);
            int v3 = bn_clip_relu(acc[mi][ni][3], a1, b1, q1);
            *(uint16_t*)(dst + (size_t)(p0 + 8) * WIDTH + co0) = (uint16_t)((v2 & 0xFF) | (v3 << 8));
        }
    }
}

// -------------------- conv1: tile 64x128, K=1024 (16 chunks) --------------------
__global__ void __launch_bounds__(256, 3) conv1_imma(const float* __restrict__ alpha,
                                                     const float* __restrict__ beta,
                                                     const int* __restrict__ q) {
    extern __shared__ int8_t smem[];
    int8_t* sA = smem;
    int8_t* sB = smem + STAGES * ABUF;
    int t = threadIdx.x, lane = t & 31, wid = t >> 5;
    int m0 = (wid >> 2) * 32, n0 = (wid & 3) * 32;
    int posBase = blockIdx.x * 64, coBase = blockIdx.y * 128;
    uint32_t sa32 = smem_u32(sA), sb32 = smem_u32(sB);
    const int8_t* gx = (const int8_t*)g_x8;
    const int8_t* gw = (const int8_t*)g_w1;

    int acc[2][4][4];
#pragma unroll
    for (int i = 0; i < 2; i++)
#pragma unroll
        for (int j = 0; j < 4; j++)
#pragma unroll
            for (int k = 0; k < 4; k++) acc[i][j][k] = 0;

    int rowA = t >> 2, offA = (t & 3) * 16;
    int rowB = t >> 1, offB = (t & 1) * 32;
    uint32_t dA = sa32 + rowA * RS + offA;
    uint32_t dB = sb32 + rowB * RS + offB;
    const int8_t* gA = gx + (size_t)(posBase + rowA) * CIN + offA;
    const int8_t* gB = gw + (size_t)(coBase + rowB) * CIN + offB;

    auto load = [&](int ch) {
        int st = ch & 3;
        CP16(dA + st * ABUF, gA + ch * 64);
        CP16(dB + st * BBUF,      gB + ch * 64);
        CP16(dB + st * BBUF + 16, gB + ch * 64 + 16);
    };

    load(0); CP_COMMIT(); load(1); CP_COMMIT(); load(2); CP_COMMIT();
    const int NCH = 16;
    for (int ch = 0; ch < NCH; ch++) {
        CP_WAIT2();
        __syncthreads();
        compute_chunk64(sa32 + (ch & 3) * ABUF, sb32 + (ch & 3) * BBUF, m0, n0, lane, acc);
        if (ch + 3 < NCH) load(ch + 3);
        CP_COMMIT();
    }
    epi_act64(acc, posBase, coBase, m0, n0, lane, alpha, beta, q, g_a1);
}

// -------------------- conv2: tile 64x128, 36 chunks --------------------
__global__ void __launch_bounds__(256, 3) conv2_imma(const float* __restrict__ alpha,
                                                     const float* __restrict__ beta,
                                                     const int* __restrict__ q) {
    extern __shared__ int8_t smem[];
    int8_t* sA = smem;
    int8_t* sB = smem + STAGES * ABUF;
    int t = threadIdx.x, lane = t & 31, wid = t >> 5;
    int m0 = (wid >> 2) * 32, n0 = (wid & 3) * 32;
    int posBase = blockIdx.x * 64, coBase = blockIdx.y * 128;
    uint32_t sa32 = smem_u32(sA), sb32 = smem_u32(sB);
    const int8_t* ga1 = (const int8_t*)g_a1;
    const int8_t* gw = (const int8_t*)g_w2;

    int acc[2][4][4];
#pragma unroll
    for (int i = 0; i < 2; i++)
#pragma unroll
        for (int j = 0; j < 4; j++)
#pragma unroll
            for (int k = 0; k < 4; k++) acc[i][j][k] = 0;

    int rowA = t >> 2, offA = (t & 3) * 16;
    int rowB = t >> 1, offB = (t & 1) * 32;
    uint32_t dA = sa32 + rowA * RS + offA;
    uint32_t dB = sb32 + rowB * RS + offB;
    int pos = posBase + rowA;
    int pimg = pos / PIX, prem = pos - pimg * PIX;
    int py = prem / 28, px = prem - py * 28;
    const int8_t* gB = gw + (size_t)(coBase + rowB) * 2304 + offB;

    auto load = [&](int ch) {
        int st = ch & 3;
        int tap = ch >> 2, kc = ch & 3;
        int dy = tap / 3 - 1, dx = tap - (tap / 3) * 3 - 1;
        int ys = py + dy, xs = px + dx;
        bool ok = (ys >= 0 && ys < 28 && xs >= 0 && xs < 28);
        const int8_t* gA = ga1 + ((size_t)(pimg * PIX + ys * 28 + xs) * WIDTH) + kc * 64 + offA;
        CP16Z(dA + st * ABUF, gA, ok);
        CP16(dB + st * BBUF,      gB + ch * 64);
        CP16(dB + st * BBUF + 16, gB + ch * 64 + 16);
    };

    load(0); CP_COMMIT(); load(1); CP_COMMIT(); load(2); CP_COMMIT();
    const int NCH = 36;
    for (int ch = 0; ch < NCH; ch++) {
        CP_WAIT2();
        __syncthreads();
        compute_chunk64(sa32 + (ch & 3) * ABUF, sb32 + (ch & 3) * BBUF, m0, n0, lane, acc);
        if (ch + 3 < NCH) load(ch + 3);
        CP_COMMIT();
    }
    epi_act64(acc, posBase, coBase, m0, n0, lane, alpha, beta, q, g_a2);
}

// -------------------- conv3: tile 128x128, K=256 (4 chunks), + residual --------------------
__global__ void __launch_bounds__(256) conv3_imma(const int* __restrict__ x,
                                                  const float* __restrict__ alpha,
                                                  const float* __restrict__ beta,
                                                  const int* __restrict__ q,
                                                  float* __restrict__ out) {
    extern __shared__ int8_t smem[];
    int8_t* sA = smem;
    int8_t* sB = smem + STAGES * BBUF;
    int t = threadIdx.x, lane = t & 31, wid = t >> 5;
    int m0 = (wid >> 2) * 64, n0 = (wid & 3) * 32;
    int posBase = blockIdx.x * 128, coBase = blockIdx.y * 128;
    uint32_t sa32 = smem_u32(sA), sb32 = smem_u32(sB);
    const int8_t* ga2 = (const int8_t*)g_a2;
    const int8_t* gw = (const int8_t*)g_w3;

    int acc[4][4][4];
#pragma unroll
    for (int i = 0; i < 4; i++)
#pragma unroll
        for (int j = 0; j < 4; j++)
#pragma unroll
            for (int k = 0; k < 4; k++) acc[i][j][k] = 0;

    int row = t >> 1, off = (t & 1) * 32;
    uint32_t dA = sa32 + row * RS + off;
    uint32_t dB = sb32 + row * RS + off;
    const int8_t* gA = ga2 + (size_t)(posBase + row) * WIDTH + off;
    const int8_t* gB = gw + (size_t)(coBase + row) * WIDTH + off;

    auto load = [&](int ch) {
        int st = ch & 3;
        CP16(dA + st * BBUF,      gA + ch * 64);
        CP16(dA + st * BBUF + 16, gA + ch * 64 + 16);
        CP16(dB + st * BBUF,      gB + ch * 64);
        CP16(dB + st * BBUF + 16, gB + ch * 64 + 16);
    };

    load(0); CP_COMMIT(); load(1); CP_COMMIT(); load(2); CP_COMMIT();
    const int NCH = 4;
    for (int ch = 0; ch < NCH; ch++) {
        CP_WAIT2();
        __syncthreads();
        compute_chunk128(sa32 + (ch & 3) * BBUF, sb32 + (ch & 3) * BBUF, m0, n0, lane, acc);
        if (ch + 3 < NCH) load(ch + 3);
        CP_COMMIT();
    }

#pragma unroll
    for (int ni = 0; ni < 4; ni++) {
        int co0 = coBase + n0 + ni * 8 + (lane & 3) * 2;
        float a0 = alpha[co0], a1 = alpha[co0 + 1];
        float b0 = beta[co0],  b1 = beta[co0 + 1];
        float q0 = exp2f((float)(q[co0] + 12)), q1 = exp2f((float)(q[co0 + 1] + 12));
#pragma unroll
        for (int mi = 0; mi < 4; mi++) {
            int p0 = posBase + m0 + mi * 16 + (lane >> 2);
#pragma unroll
            for (int half = 0; half < 2; half++) {
                int p = p0 + half * 8;
                int n = p / PIX, rem = p - n * PIX;
                size_t gi0 = ((size_t)n * COUT + co0) * PIX + rem;
                size_t gi1 = gi0 + PIX;
                float v0 = bn_clip(acc[mi][ni][half * 2],     a0, b0, q0);
                float v1 = bn_clip(acc[mi][ni][half * 2 + 1], a1, b1, q1);
                float s0 = v0 + (float)x[gi0];
                float s1 = v1 + (float)x[gi1];
                out[gi0] = fminf(fmaxf(s0, 0.0f), 127.0f);
                out[gi1] = fminf(fmaxf(s1, 0.0f), 127.0f);
            }
        }
    }
}

// -------------------- launch --------------------
extern "C" void kernel_launch(void* const* d_in, const int* in_sizes, int n_in,
                              void* d_out, int out_size) {
    const int*   x   = (const int*)d_in[0];
    const float* w21 = (const float*)d_in[1];
    const int*   s1  = (const int*)d_in[2];
    const float* w22 = (const float*)d_in[3];
    const int*   s2  = (const int*)d_in[4];
    const float* w23 = (const float*)d_in[5];
    const int*   s3  = (const int*)d_in[6];
    const float* al1 = (const float*)d_in[7];
    const float* be1 = (const float*)d_in[8];
    const int*   q1  = (const int*)d_in[9];
    const float* al2 = (const float*)d_in[10];
    const float* be2 = (const float*)d_in[11];
    const int*   q2  = (const int*)d_in[12];
    const float* al3 = (const float*)d_in[13];
    const float* be3 = (const float*)d_in[14];
    const int*   q3  = (const int*)d_in[15];
    float* out = (float*)d_out;

    cudaFuncSetAttribute(conv1_imma, cudaFuncAttributeMaxDynamicSharedMemorySize, SMEM12);
    cudaFuncSetAttribute(conv2_imma, cudaFuncAttributeMaxDynamicSharedMemorySize, SMEM12);
    cudaFuncSetAttribute(conv3_imma, cudaFuncAttributeMaxDynamicSharedMemorySize, SMEM3);

    pack_all_kernel<<<(W1W + W2W + W3W + 255) / 256, 256>>>(w21, s1, w22, s2, w23, s3);
    xpose_kernel<<<dim3(25, 8, 16), 256>>>(x);

    conv1_imma<<<dim3(196, 2), 256, SMEM12>>>(al1, be1, q1);
    conv2_imma<<<dim3(196, 2), 256, SMEM12>>>(al2, be2, q2);
    conv3_imma<<<dim3(98, 8), 256, SMEM3>>>(x, al3, be3, q3, out);
}